// round 9
// baseline (speedup 1.0000x reference)
#include <cuda_runtime.h>
#include <cuda_fp16.h>
#include <cuda_bf16.h>

#define DB 8
#define DN 8192
#define DE 131072
#define DD 128
// 65536 rows total

__device__ float         g_h[DB * DN * DD];    // 32 MB: linear output (fp32)
__device__ __half        g_hh[DB * DN * DD];   // 16 MB: fp16 copy for gathers
__device__ __nv_bfloat16 g_Whi[DD * DD];       // W split hi, [k][n]
__device__ __nv_bfloat16 g_Wlo[DD * DD];       // W split lo, [k][n]
__device__ int           g_cnt[DB * DN];       // per-dst edge counts
__device__ int           g_off[DB * DN];       // CSR start offsets
__device__ int           g_cur[DB * DN];       // scatter cursors
__device__ int           g_srt[DB * DE];       // src indices sorted by dst
__device__ int           g_base[DB];           // per-batch region allocator
__device__ int           g_is64;               // edge_index dtype flag

// ---------------------------------------------------------------------------
// setup: detect idx dtype + zero counters + split W to bf16 hi/lo planes.
// g_Whi[k][n] = bf16(W[n][k]); g_Wlo = bf16(residual).
// ---------------------------------------------------------------------------
__global__ void setup_kernel(const unsigned* __restrict__ eiw,
                             const float* __restrict__ W) {
    int t = blockIdx.x * 256 + threadIdx.x;   // 65536 threads
    g_cnt[t] = 0;
    if (t < DB) g_base[t] = 0;
    if (t < DD * DD) {
        int k = t & 127;
        int n = t >> 7;
        float v = W[n * DD + k];
        __nv_bfloat16 hi = __float2bfloat16_rn(v);
        __nv_bfloat16 lo = __float2bfloat16_rn(v - __bfloat162float(hi));
        g_Whi[k * DD + n] = hi;
        g_Wlo[k * DD + n] = lo;
    }
    if (t == 0) {
        // int64 values < 8192 -> all odd 32-bit words zero (little-endian)
        int ok = 1;
        for (int i = 0; i < 64; i++)
            if (eiw[2 * i + 1] != 0u) { ok = 0; break; }
        g_is64 = ok;
    }
}

__device__ __forceinline__ int load_idx(const void* ei, size_t p) {
    return g_is64 ? (int)((const long long*)ei)[p] : ((const int*)ei)[p];
}

// ---------------------------------------------------------------------------
// histogram of dst degrees
// ---------------------------------------------------------------------------
__global__ void hist_kernel(const void* __restrict__ ei) {
    int t = blockIdx.x * 256 + threadIdx.x;    // [0, DB*DE)
    int b = t >> 17;
    int e = t & (DE - 1);
    int dst = load_idx(ei, ((size_t)b * 2 + 1) * DE + e);
    if ((unsigned)dst < DN) atomicAdd(&g_cnt[b * DN + dst], 1);
}

// ---------------------------------------------------------------------------
// region allocation: warp-scan + one atomicAdd per warp per batch cursor.
// ---------------------------------------------------------------------------
__global__ void alloc_kernel() {
    int node = blockIdx.x * 256 + threadIdx.x;   // [0, 65536)
    int lane = threadIdx.x & 31;
    int b = node >> 13;
    int cnt = g_cnt[node];
    int incl = cnt;
#pragma unroll
    for (int o = 1; o < 32; o <<= 1) {
        int n = __shfl_up_sync(0xFFFFFFFFu, incl, o);
        if (lane >= o) incl += n;
    }
    int total = __shfl_sync(0xFFFFFFFFu, incl, 31);
    int base = 0;
    if (lane == 31) base = atomicAdd(&g_base[b], total);
    base = __shfl_sync(0xFFFFFFFFu, base, 31);
    int off = base + incl - cnt;
    g_off[node] = off;
    g_cur[node] = off;
}

// ---------------------------------------------------------------------------
// scatter src ids into dst-sorted order
// ---------------------------------------------------------------------------
__global__ void scatter_kernel(const void* __restrict__ ei) {
    int t = blockIdx.x * 256 + threadIdx.x;    // [0, DB*DE)
    int b = t >> 17;
    int e = t & (DE - 1);
    int src = load_idx(ei, (size_t)b * 2 * DE + e);
    int dst = load_idx(ei, ((size_t)b * 2 + 1) * DE + e);
    if ((unsigned)src >= DN || (unsigned)dst >= DN) return;
    int pos = atomicAdd(&g_cur[b * DN + dst], 1);
    g_srt[(size_t)b * DE + pos] = src;
}

// ---------------------------------------------------------------------------
// Tensor-core GEMM: h = x @ W^T + b via bf16 split (hi+lo) mma.sync.
// Block = 256 thr, 64-row tile; warp = 16 rows x 64 cols (4 m-tiles x 2
// n-halves). smem = W hi/lo (64 KB) + X hi/lo (32 KB) = 96 KB -> 2 blocks/SM,
// 4 warps/SMSP. XOR-swizzle (16B chunk j ^= row&7) -> conflict-free ldmatrix.
// ---------------------------------------------------------------------------
__device__ __forceinline__ void ldsm_x4(unsigned* r, unsigned addr) {
    asm volatile("ldmatrix.sync.aligned.m8n8.x4.shared.b16 {%0,%1,%2,%3}, [%4];"
                 : "=r"(r[0]), "=r"(r[1]), "=r"(r[2]), "=r"(r[3]) : "r"(addr));
}
__device__ __forceinline__ void ldsm_x4_t(unsigned* r, unsigned addr) {
    asm volatile("ldmatrix.sync.aligned.m8n8.x4.trans.shared.b16 {%0,%1,%2,%3}, [%4];"
                 : "=r"(r[0]), "=r"(r[1]), "=r"(r[2]), "=r"(r[3]) : "r"(addr));
}
__device__ __forceinline__ void mma_bf16(float* c, const unsigned* a,
                                         unsigned b0, unsigned b1) {
    asm("mma.sync.aligned.m16n8k16.row.col.f32.bf16.bf16.f32 "
        "{%0,%1,%2,%3}, {%4,%5,%6,%7}, {%8,%9}, {%0,%1,%2,%3};"
        : "+f"(c[0]), "+f"(c[1]), "+f"(c[2]), "+f"(c[3])
        : "r"(a[0]), "r"(a[1]), "r"(a[2]), "r"(a[3]), "r"(b0), "r"(b1));
}

__device__ __forceinline__ void split8(float4 f0, float4 f1, uint4& hi, uint4& lo) {
    float f[8] = {f0.x, f0.y, f0.z, f0.w, f1.x, f1.y, f1.z, f1.w};
    unsigned h[4], l[4];
#pragma unroll
    for (int i = 0; i < 4; i++) {
        __nv_bfloat162 hh = __floats2bfloat162_rn(f[2 * i], f[2 * i + 1]);
        float r0 = f[2 * i]     - __bfloat162float(hh.x);
        float r1 = f[2 * i + 1] - __bfloat162float(hh.y);
        __nv_bfloat162 ll = __floats2bfloat162_rn(r0, r1);
        h[i] = *(unsigned*)&hh;
        l[i] = *(unsigned*)&ll;
    }
    hi = make_uint4(h[0], h[1], h[2], h[3]);
    lo = make_uint4(l[0], l[1], l[2], l[3]);
}

__global__ void __launch_bounds__(256, 2)
gemm_kernel(const float* __restrict__ x, const float* __restrict__ bias) {
    extern __shared__ char smc[];
    __nv_bfloat16* sWhi = (__nv_bfloat16*)smc;              // [128][128] swz (+32768B lo)
    __nv_bfloat16* sXhi = (__nv_bfloat16*)(smc + 65536);    // [64][128]  swz (+16384B lo)

    int tid = threadIdx.x;
    int row0 = blockIdx.x * 64;

    // copy pre-split W planes (bf16), 16B chunks with swizzle
    for (int c = tid; c < 2048; c += 256) {
        int row = c >> 4, j = c & 15;
        int off = row * DD + ((j ^ (row & 7)) << 3);
        *(uint4*)(sWhi + off)                  = *(const uint4*)(g_Whi + row * DD + j * 8);
        *(uint4*)((char*)(sWhi + off) + 32768) = *(const uint4*)(g_Wlo + row * DD + j * 8);
    }
    // load + split X (64 rows)
    for (int c = tid; c < 1024; c += 256) {
        int row = c >> 4, j = c & 15;
        const float4* p = (const float4*)(x + (size_t)(row0 + row) * DD + j * 8);
        uint4 hi, lo;
        split8(p[0], p[1], hi, lo);
        int off = row * DD + ((j ^ (row & 7)) << 3);
        *(uint4*)(sXhi + off)                  = hi;
        *(uint4*)((char*)(sXhi + off) + 16384) = lo;
    }
    __syncthreads();

    int warp = tid >> 5, lane = tid & 31;
    int m0 = (warp >> 1) * 16;        // 0,16,32,48
    int nh = warp & 1;                // n-half: cols nh*64 .. nh*64+63
    int l15 = lane & 15, lh = lane >> 4;

    int arow = m0 + l15;
    unsigned xbhi = (unsigned)__cvta_generic_to_shared(sXhi) + arow * 256;
    unsigned xsw = (unsigned)(arow & 7);
    unsigned wb = (unsigned)__cvta_generic_to_shared(sWhi);

    float acc[8][4];
#pragma unroll
    for (int t = 0; t < 8; t++)
#pragma unroll
        for (int i = 0; i < 4; i++) acc[t][i] = 0.f;

#pragma unroll
    for (int kt = 0; kt < 8; kt++) {
        unsigned ahi[4], alo[4];
        unsigned achunk = (((unsigned)(2 * kt + lh)) ^ xsw) << 4;
        ldsm_x4(ahi, xbhi + achunk);
        ldsm_x4(alo, xbhi + achunk + 16384u);
        int brow = kt * 16 + l15;
        unsigned bb = wb + brow * 256;
        unsigned bsw = (unsigned)(brow & 7);
#pragma unroll
        for (int t2 = 0; t2 < 4; t2++) {
            unsigned bhi[4], blo[4];
            unsigned bchunk = (((unsigned)(nh * 8 + 2 * t2 + lh)) ^ bsw) << 4;
            ldsm_x4_t(bhi, bb + bchunk);
            ldsm_x4_t(blo, bb + bchunk + 32768u);
            mma_bf16(acc[2 * t2],     ahi, bhi[0], bhi[1]);
            mma_bf16(acc[2 * t2 + 1], ahi, bhi[2], bhi[3]);
            mma_bf16(acc[2 * t2],     alo, bhi[0], bhi[1]);
            mma_bf16(acc[2 * t2 + 1], alo, bhi[2], bhi[3]);
            mma_bf16(acc[2 * t2],     ahi, blo[0], blo[1]);
            mma_bf16(acc[2 * t2 + 1], ahi, blo[2], blo[3]);
        }
    }

    // epilogue: C frag lane mapping: rows g, g+8; cols nh*64 + 8t + 2q (+1)
    int g = lane >> 2;
    int q = lane & 3;
    size_t r0g = (size_t)(row0 + m0 + g) * DD;
    float*  h0  = g_h  + r0g;
    float*  h1  = h0 + 8 * DD;
    __half* hh0 = g_hh + r0g;
    __half* hh1 = hh0 + 8 * DD;
#pragma unroll
    for (int t = 0; t < 8; t++) {
        int n = nh * 64 + 8 * t + 2 * q;
        float2 bv = *(const float2*)(bias + n);
        float2 v0 = make_float2(acc[t][0] + bv.x, acc[t][1] + bv.y);
        float2 v1 = make_float2(acc[t][2] + bv.x, acc[t][3] + bv.y);
        *(float2*)(h0 + n) = v0;
        *(float2*)(h1 + n) = v1;
        *(__half2*)(hh0 + n) = __floats2half2_rn(v0.x, v0.y);
        *(__half2*)(hh1 + n) = __floats2half2_rn(v1.x, v1.y);
    }
}

// ---------------------------------------------------------------------------
// Fused: CSR gather of incident src rows (fp16), + fp32 h, LN, ReLU, mask.
// One warp per node; lane owns 4 consecutive cols.
// ---------------------------------------------------------------------------
__global__ void agg_ln_kernel(const float* __restrict__ mask,
                              const float* __restrict__ gamma,
                              const float* __restrict__ beta,
                              float* __restrict__ out) {
    int w = (blockIdx.x * 256 + threadIdx.x) >> 5;   // node id [0, 65536)
    int lane = threadIdx.x & 31;
    int b = w >> 13;

    int start = g_off[w];
    int cnt = g_cnt[w];
    int end = start + cnt;
    const int* srt = g_srt + (size_t)b * DE;
    const __half* hb = g_hh + (size_t)b * DN * DD;

    float4 acc = make_float4(0.f, 0.f, 0.f, 0.f);
    int j = start;
    for (; j + 4 <= end; j += 4) {
        int s0 = srt[j], s1 = srt[j + 1], s2 = srt[j + 2], s3 = srt[j + 3];
        uint2 r0 = ((const uint2*)(hb + (size_t)s0 * DD))[lane];
        uint2 r1 = ((const uint2*)(hb + (size_t)s1 * DD))[lane];
        uint2 r2 = ((const uint2*)(hb + (size_t)s2 * DD))[lane];
        uint2 r3 = ((const uint2*)(hb + (size_t)s3 * DD))[lane];
        float2 a0 = __half22float2(*(__half2*)&r0.x), b0 = __half22float2(*(__half2*)&r0.y);
        float2 a1 = __half22float2(*(__half2*)&r1.x), b1 = __half22float2(*(__half2*)&r1.y);
        float2 a2 = __half22float2(*(__half2*)&r2.x), b2 = __half22float2(*(__half2*)&r2.y);
        float2 a3 = __half22float2(*(__half2*)&r3.x), b3 = __half22float2(*(__half2*)&r3.y);
        acc.x += (a0.x + a1.x) + (a2.x + a3.x);
        acc.y += (a0.y + a1.y) + (a2.y + a3.y);
        acc.z += (b0.x + b1.x) + (b2.x + b3.x);
        acc.w += (b0.y + b1.y) + (b2.y + b3.y);
    }
    for (; j < end; j++) {
        int s0 = srt[j];
        uint2 r0 = ((const uint2*)(hb + (size_t)s0 * DD))[lane];
        float2 a0 = __half22float2(*(__half2*)&r0.x), b0 = __half22float2(*(__half2*)&r0.y);
        acc.x += a0.x; acc.y += a0.y; acc.z += b0.x; acc.w += b0.y;
    }

    float4 h = ((const float4*)(g_h + (size_t)w * DD))[lane];
    const float s = 0.011048543456039806f;  // 1/sqrt(8192)
    float4 v;
    v.x = h.x + acc.x * s;
    v.y = h.y + acc.y * s;
    v.z = h.z + acc.z * s;
    v.w = h.w + acc.w * s;

    float sum = v.x + v.y + v.z + v.w;
    float ssq = v.x * v.x + v.y * v.y + v.z * v.z + v.w * v.w;
#pragma unroll
    for (int o = 16; o > 0; o >>= 1) {
        sum += __shfl_xor_sync(0xFFFFFFFFu, sum, o);
        ssq += __shfl_xor_sync(0xFFFFFFFFu, ssq, o);
    }
    float mu = sum * (1.0f / 128.0f);
    float var = ssq * (1.0f / 128.0f) - mu * mu;
    float rstd = rsqrtf(var + 1e-5f);
    float m = mask[w];

    float4 gg = ((const float4*)gamma)[lane];
    float4 be = ((const float4*)beta)[lane];
    float4 o4;
    o4.x = fmaxf((v.x - mu) * rstd * gg.x + be.x, 0.f) * m;
    o4.y = fmaxf((v.y - mu) * rstd * gg.y + be.y, 0.f) * m;
    o4.z = fmaxf((v.z - mu) * rstd * gg.z + be.z, 0.f) * m;
    o4.w = fmaxf((v.w - mu) * rstd * gg.w + be.w, 0.f) * m;

    ((float4*)out)[(size_t)w * 32 + lane] = o4;
}

// ---------------------------------------------------------------------------
extern "C" void kernel_launch(void* const* d_in, const int* in_sizes, int n_in,
                              void* d_out, int out_size) {
    const float* xf     = (const float*)d_in[0];   // node_features [8,8192,128]
    const void*  ei     = d_in[1];                 // edge_index [8,2,131072]
    const float* mask   = (const float*)d_in[2];   // node_mask [8,8192]
    const float* W      = (const float*)d_in[3];   // W [128,128]
    const float* bias   = (const float*)d_in[4];   // b [128]
    const float* gamma  = (const float*)d_in[5];   // gamma [128]
    const float* beta   = (const float*)d_in[6];   // beta [128]
    float* out          = (float*)d_out;

    const int smem_bytes = 98304;  // W hi/lo 64 KB + X hi/lo 32 KB
    cudaFuncSetAttribute(gemm_kernel, cudaFuncAttributeMaxDynamicSharedMemorySize, smem_bytes);

    setup_kernel<<<(DB * DN) / 256, 256>>>((const unsigned*)ei, W);
    hist_kernel<<<(DB * DE) / 256, 256>>>(ei);
    alloc_kernel<<<(DB * DN) / 256, 256>>>();
    gemm_kernel<<<(DB * DN) / 64, 256, smem_bytes>>>(xf, bias);    // 1024 blocks
    scatter_kernel<<<(DB * DE) / 256, 256>>>(ei);
    agg_ln_kernel<<<(DB * DN) / 8, 256>>>(mask, gamma, beta, out); // 8192 blocks
}

// round 15
// speedup vs baseline: 1.2467x; 1.2467x over previous
#include <cuda_runtime.h>
#include <cuda_fp16.h>
#include <cuda_bf16.h>

#define DB 8
#define DN 8192
#define DE 131072
#define DD 128
// 65536 rows total, 512 tiles of 128 rows

__device__ float         g_h[DB * DN * DD];    // 32 MB: linear output (fp32)
__device__ __half        g_hh[DB * DN * DD];   // 16 MB: fp16 copy for gathers
__device__ __nv_bfloat16 g_Whi[DD * DD];       // W split hi, k-major [k][n]
__device__ __nv_bfloat16 g_Wlo[DD * DD];       // W split lo, k-major [k][n]
__device__ int           g_cnt[DB * DN];       // per-dst edge counts
__device__ int           g_off[DB * DN];       // CSR start offsets
__device__ int           g_cur[DB * DN];       // scatter cursors
__device__ int           g_srt[DB * DE];       // src indices sorted by dst
__device__ int           g_base[DB];           // per-batch region allocator
__device__ int           g_is64;               // edge_index dtype flag

// ---------------------------------------------------------------------------
// setup: detect idx dtype + zero counters + split W to bf16 hi/lo k-major.
// ---------------------------------------------------------------------------
__global__ void setup_kernel(const unsigned* __restrict__ eiw,
                             const float* __restrict__ W) {
    int t = blockIdx.x * 256 + threadIdx.x;   // 65536 threads
    g_cnt[t] = 0;
    if (t < DB) g_base[t] = 0;
    if (t < DD * DD) {
        int k = t & 127;
        int n = t >> 7;
        float v = W[n * DD + k];
        __nv_bfloat16 hi = __float2bfloat16_rn(v);
        __nv_bfloat16 lo = __float2bfloat16_rn(v - __bfloat162float(hi));
        g_Whi[k * DD + n] = hi;
        g_Wlo[k * DD + n] = lo;
    }
    if (t == 0) {
        // int64 values < 8192 -> all odd 32-bit words zero (little-endian)
        int ok = 1;
        for (int i = 0; i < 64; i++)
            if (eiw[2 * i + 1] != 0u) { ok = 0; break; }
        g_is64 = ok;
    }
}

__device__ __forceinline__ int load_idx(const void* ei, size_t p) {
    return g_is64 ? (int)((const long long*)ei)[p] : ((const int*)ei)[p];
}

// ---------------------------------------------------------------------------
// histogram of dst degrees
// ---------------------------------------------------------------------------
__global__ void hist_kernel(const void* __restrict__ ei) {
    int t = blockIdx.x * 256 + threadIdx.x;    // [0, DB*DE)
    int b = t >> 17;
    int e = t & (DE - 1);
    int dst = load_idx(ei, ((size_t)b * 2 + 1) * DE + e);
    if ((unsigned)dst < DN) atomicAdd(&g_cnt[b * DN + dst], 1);
}

// ---------------------------------------------------------------------------
// region allocation: warp-scan + one atomicAdd per warp per batch cursor.
// ---------------------------------------------------------------------------
__global__ void alloc_kernel() {
    int node = blockIdx.x * 256 + threadIdx.x;   // [0, 65536)
    int lane = threadIdx.x & 31;
    int b = node >> 13;
    int cnt = g_cnt[node];
    int incl = cnt;
#pragma unroll
    for (int o = 1; o < 32; o <<= 1) {
        int n = __shfl_up_sync(0xFFFFFFFFu, incl, o);
        if (lane >= o) incl += n;
    }
    int total = __shfl_sync(0xFFFFFFFFu, incl, 31);
    int base = 0;
    if (lane == 31) base = atomicAdd(&g_base[b], total);
    base = __shfl_sync(0xFFFFFFFFu, base, 31);
    int off = base + incl - cnt;
    g_off[node] = off;
    g_cur[node] = off;
}

// ---------------------------------------------------------------------------
// Tensor-core GEMM (mma.sync, bf16 3-term split) FUSED with edge scatter.
// Blocks [0,512): one 128-row GEMM tile each (R8 config, proven).
// Blocks [512,1024): scatter src ids into dst-sorted order (backfills SMs).
// ---------------------------------------------------------------------------
__device__ __forceinline__ void ldsm_x4(unsigned* r, unsigned addr) {
    asm volatile("ldmatrix.sync.aligned.m8n8.x4.shared.b16 {%0,%1,%2,%3}, [%4];"
                 : "=r"(r[0]), "=r"(r[1]), "=r"(r[2]), "=r"(r[3]) : "r"(addr));
}
__device__ __forceinline__ void ldsm_x4_t(unsigned* r, unsigned addr) {
    asm volatile("ldmatrix.sync.aligned.m8n8.x4.trans.shared.b16 {%0,%1,%2,%3}, [%4];"
                 : "=r"(r[0]), "=r"(r[1]), "=r"(r[2]), "=r"(r[3]) : "r"(addr));
}
__device__ __forceinline__ void mma_bf16(float* c, const unsigned* a,
                                         unsigned b0, unsigned b1) {
    asm("mma.sync.aligned.m16n8k16.row.col.f32.bf16.bf16.f32 "
        "{%0,%1,%2,%3}, {%4,%5,%6,%7}, {%8,%9}, {%0,%1,%2,%3};"
        : "+f"(c[0]), "+f"(c[1]), "+f"(c[2]), "+f"(c[3])
        : "r"(a[0]), "r"(a[1]), "r"(a[2]), "r"(a[3]), "r"(b0), "r"(b1));
}

__device__ __forceinline__ void split8(float4 f0, float4 f1, uint4& hi, uint4& lo) {
    float f[8] = {f0.x, f0.y, f0.z, f0.w, f1.x, f1.y, f1.z, f1.w};
    unsigned h[4], l[4];
#pragma unroll
    for (int i = 0; i < 4; i++) {
        __nv_bfloat162 hh = __floats2bfloat162_rn(f[2 * i], f[2 * i + 1]);
        float r0 = f[2 * i]     - __bfloat162float(hh.x);
        float r1 = f[2 * i + 1] - __bfloat162float(hh.y);
        __nv_bfloat162 ll = __floats2bfloat162_rn(r0, r1);
        h[i] = *(unsigned*)&hh;
        l[i] = *(unsigned*)&ll;
    }
    hi = make_uint4(h[0], h[1], h[2], h[3]);
    lo = make_uint4(l[0], l[1], l[2], l[3]);
}

__global__ void __launch_bounds__(256)
gemm_scatter_kernel(const float* __restrict__ x, const float* __restrict__ bias,
                    const void* __restrict__ ei) {
    // ---- scatter blocks -------------------------------------------------
    if (blockIdx.x >= 512) {
        int tbase = (blockIdx.x - 512) * 256 + threadIdx.x;   // [0, 131072)
#pragma unroll
        for (int i = 0; i < 8; i++) {
            int t = tbase + i * 131072;                       // [0, DB*DE)
            int b = t >> 17;
            int e = t & (DE - 1);
            int src = load_idx(ei, (size_t)b * 2 * DE + e);
            int dst = load_idx(ei, ((size_t)b * 2 + 1) * DE + e);
            if ((unsigned)src >= DN || (unsigned)dst >= DN) continue;
            int pos = atomicAdd(&g_cur[b * DN + dst], 1);
            g_srt[(size_t)b * DE + pos] = src;
        }
        return;
    }

    // ---- GEMM blocks (R8 config) ---------------------------------------
    extern __shared__ char smc[];
    __nv_bfloat16* sWhi = (__nv_bfloat16*)smc;              // [128][128] swz (+32768B lo)
    __nv_bfloat16* sXhi = (__nv_bfloat16*)(smc + 65536);    // [128][128] swz (+32768B lo)

    int tid = threadIdx.x;
    int row0 = blockIdx.x * 128;

    // copy pre-split W planes (bf16, k-major), 16B chunks with swizzle
    for (int c = tid; c < 2048; c += 256) {
        int row = c >> 4, j = c & 15;
        int off = row * DD + ((j ^ (row & 7)) << 3);
        *(uint4*)(sWhi + off)                  = *(const uint4*)(g_Whi + row * DD + j * 8);
        *(uint4*)((char*)(sWhi + off) + 32768) = *(const uint4*)(g_Wlo + row * DD + j * 8);
    }
    // load + split X (128 rows)
    for (int c = tid; c < 2048; c += 256) {
        int row = c >> 4, j = c & 15;
        const float4* p = (const float4*)(x + (size_t)(row0 + row) * DD + j * 8);
        uint4 hi, lo;
        split8(p[0], p[1], hi, lo);
        int off = row * DD + ((j ^ (row & 7)) << 3);
        *(uint4*)(sXhi + off)                  = hi;
        *(uint4*)((char*)(sXhi + off) + 32768) = lo;
    }
    __syncthreads();

    int warp = tid >> 5, lane = tid & 31;
    int m0 = warp * 16;
    int l15 = lane & 15, lh = lane >> 4;

    int arow = m0 + l15;
    unsigned xbhi = (unsigned)__cvta_generic_to_shared(sXhi) + arow * 256;
    unsigned xsw = (unsigned)(arow & 7);
    unsigned wb = (unsigned)__cvta_generic_to_shared(sWhi);

    float acc[16][4];
#pragma unroll
    for (int t = 0; t < 16; t++)
#pragma unroll
        for (int i = 0; i < 4; i++) acc[t][i] = 0.f;

#pragma unroll
    for (int kt = 0; kt < 8; kt++) {
        unsigned ahi[4], alo[4];
        unsigned achunk = (((unsigned)(2 * kt + lh)) ^ xsw) << 4;
        ldsm_x4(ahi, xbhi + achunk);
        ldsm_x4(alo, xbhi + achunk + 32768u);
        int brow = kt * 16 + l15;
        unsigned bb = wb + brow * 256;
        unsigned bsw = (unsigned)(brow & 7);
#pragma unroll
        for (int t2 = 0; t2 < 8; t2++) {
            unsigned bhi[4], blo[4];
            unsigned bchunk = (((unsigned)(2 * t2 + lh)) ^ bsw) << 4;
            ldsm_x4_t(bhi, bb + bchunk);
            ldsm_x4_t(blo, bb + bchunk + 32768u);
            mma_bf16(acc[2 * t2],     ahi, bhi[0], bhi[1]);
            mma_bf16(acc[2 * t2 + 1], ahi, bhi[2], bhi[3]);
            mma_bf16(acc[2 * t2],     alo, bhi[0], bhi[1]);
            mma_bf16(acc[2 * t2 + 1], alo, bhi[2], bhi[3]);
            mma_bf16(acc[2 * t2],     ahi, blo[0], blo[1]);
            mma_bf16(acc[2 * t2 + 1], ahi, blo[2], blo[3]);
        }
    }

    // epilogue: C frag lane mapping: rows g, g+8; cols 8t + 2q (+1)
    int g = lane >> 2;
    int q = lane & 3;
    size_t r0g = (size_t)(row0 + m0 + g) * DD;
    float*  h0  = g_h  + r0g;
    float*  h1  = h0 + 8 * DD;
    __half* hh0 = g_hh + r0g;
    __half* hh1 = hh0 + 8 * DD;
#pragma unroll
    for (int t = 0; t < 16; t++) {
        int n = 8 * t + 2 * q;
        float2 bv = *(const float2*)(bias + n);
        float2 v0 = make_float2(acc[t][0] + bv.x, acc[t][1] + bv.y);
        float2 v1 = make_float2(acc[t][2] + bv.x, acc[t][3] + bv.y);
        *(float2*)(h0 + n) = v0;
        *(float2*)(h1 + n) = v1;
        *(__half2*)(hh0 + n) = __floats2half2_rn(v0.x, v0.y);
        *(__half2*)(hh1 + n) = __floats2half2_rn(v1.x, v1.y);
    }
}

// ---------------------------------------------------------------------------
// Fused: CSR gather of incident src rows (fp16), + fp32 h, LN, ReLU, mask.
// One warp per node; 8 rows in flight per iteration for L2-latency hiding.
// ---------------------------------------------------------------------------
__global__ void agg_ln_kernel(const float* __restrict__ mask,
                              const float* __restrict__ gamma,
                              const float* __restrict__ beta,
                              float* __restrict__ out) {
    int w = (blockIdx.x * 256 + threadIdx.x) >> 5;   // node id [0, 65536)
    int lane = threadIdx.x & 31;
    int b = w >> 13;

    int start = g_off[w];
    int cnt = g_cnt[w];
    int end = start + cnt;
    const int* srt = g_srt + (size_t)b * DE;
    const __half* hb = g_hh + (size_t)b * DN * DD;

    float4 acc = make_float4(0.f, 0.f, 0.f, 0.f);
    int j = start;
    for (; j + 8 <= end; j += 8) {
        int s[8];
#pragma unroll
        for (int i = 0; i < 8; i++) s[i] = srt[j + i];
        uint2 r[8];
#pragma unroll
        for (int i = 0; i < 8; i++)
            r[i] = ((const uint2*)(hb + (size_t)s[i] * DD))[lane];
#pragma unroll
        for (int i = 0; i < 8; i++) {
            float2 a = __half22float2(*(__half2*)&r[i].x);
            float2 c = __half22float2(*(__half2*)&r[i].y);
            acc.x += a.x; acc.y += a.y; acc.z += c.x; acc.w += c.y;
        }
    }
    for (; j + 4 <= end; j += 4) {
        int s[4];
#pragma unroll
        for (int i = 0; i < 4; i++) s[i] = srt[j + i];
        uint2 r[4];
#pragma unroll
        for (int i = 0; i < 4; i++)
            r[i] = ((const uint2*)(hb + (size_t)s[i] * DD))[lane];
#pragma unroll
        for (int i = 0; i < 4; i++) {
            float2 a = __half22float2(*(__half2*)&r[i].x);
            float2 c = __half22float2(*(__half2*)&r[i].y);
            acc.x += a.x; acc.y += a.y; acc.z += c.x; acc.w += c.y;
        }
    }
    for (; j < end; j++) {
        int s0 = srt[j];
        uint2 r0 = ((const uint2*)(hb + (size_t)s0 * DD))[lane];
        float2 a0 = __half22float2(*(__half2*)&r0.x), b0 = __half22float2(*(__half2*)&r0.y);
        acc.x += a0.x; acc.y += a0.y; acc.z += b0.x; acc.w += b0.y;
    }

    float4 h = ((const float4*)(g_h + (size_t)w * DD))[lane];
    const float s = 0.011048543456039806f;  // 1/sqrt(8192)
    float4 v;
    v.x = h.x + acc.x * s;
    v.y = h.y + acc.y * s;
    v.z = h.z + acc.z * s;
    v.w = h.w + acc.w * s;

    float sum = v.x + v.y + v.z + v.w;
    float ssq = v.x * v.x + v.y * v.y + v.z * v.z + v.w * v.w;
#pragma unroll
    for (int o = 16; o > 0; o >>= 1) {
        sum += __shfl_xor_sync(0xFFFFFFFFu, sum, o);
        ssq += __shfl_xor_sync(0xFFFFFFFFu, ssq, o);
    }
    float mu = sum * (1.0f / 128.0f);
    float var = ssq * (1.0f / 128.0f) - mu * mu;
    float rstd = rsqrtf(var + 1e-5f);
    float m = mask[w];

    float4 gg = ((const float4*)gamma)[lane];
    float4 be = ((const float4*)beta)[lane];
    float4 o4;
    o4.x = fmaxf((v.x - mu) * rstd * gg.x + be.x, 0.f) * m;
    o4.y = fmaxf((v.y - mu) * rstd * gg.y + be.y, 0.f) * m;
    o4.z = fmaxf((v.z - mu) * rstd * gg.z + be.z, 0.f) * m;
    o4.w = fmaxf((v.w - mu) * rstd * gg.w + be.w, 0.f) * m;

    ((float4*)out)[(size_t)w * 32 + lane] = o4;
}

// ---------------------------------------------------------------------------
extern "C" void kernel_launch(void* const* d_in, const int* in_sizes, int n_in,
                              void* d_out, int out_size) {
    const float* xf     = (const float*)d_in[0];   // node_features [8,8192,128]
    const void*  ei     = d_in[1];                 // edge_index [8,2,131072]
    const float* mask   = (const float*)d_in[2];   // node_mask [8,8192]
    const float* W      = (const float*)d_in[3];   // W [128,128]
    const float* bias   = (const float*)d_in[4];   // b [128]
    const float* gamma  = (const float*)d_in[5];   // gamma [128]
    const float* beta   = (const float*)d_in[6];   // beta [128]
    float* out          = (float*)d_out;

    const int smem_bytes = 131072;  // 4 x 32 KB bf16 planes
    cudaFuncSetAttribute(gemm_scatter_kernel,
                         cudaFuncAttributeMaxDynamicSharedMemorySize, smem_bytes);

    setup_kernel<<<(DB * DN) / 256, 256>>>((const unsigned*)ei, W);
    hist_kernel<<<(DB * DE) / 256, 256>>>(ei);
    alloc_kernel<<<(DB * DN) / 256, 256>>>();
    gemm_scatter_kernel<<<1024, 256, smem_bytes>>>(xf, bias, ei);  // 512 gemm + 512 scatter
    agg_ln_kernel<<<(DB * DN) / 8, 256>>>(mask, gamma, beta, out); // 8192 blocks
}

// round 16
// speedup vs baseline: 1.4297x; 1.1468x over previous
#include <cuda_runtime.h>
#include <cuda_fp16.h>
#include <cuda_bf16.h>

#define DB 8
#define DN 8192
#define DE 131072
#define DD 128
// 65536 rows total, 512 tiles of 128 rows

__device__ float         g_h[DB * DN * DD];    // 32 MB: linear output (fp32)
__device__ __half        g_hh[DB * DN * DD];   // 16 MB: fp16 copy for gathers
__device__ __nv_bfloat16 g_Whi[DD * DD];       // W split hi, k-major [k][n]
__device__ __nv_bfloat16 g_Wlo[DD * DD];       // W split lo, k-major [k][n]
__device__ int           g_cnt[DB * DN];       // per-dst edge counts
__device__ int           g_off[DB * DN];       // CSR start offsets
__device__ int           g_cur[DB * DN];       // scatter cursors
__device__ int           g_srt[DB * DE];       // src indices sorted by dst
__device__ int           g_base[DB];           // per-batch region allocator
__device__ int           g_is64;               // edge_index dtype flag

// ---------------------------------------------------------------------------
// setup: detect idx dtype + zero counters + split W to bf16 hi/lo k-major.
// ---------------------------------------------------------------------------
__global__ void setup_kernel(const unsigned* __restrict__ eiw,
                             const float* __restrict__ W) {
    int t = blockIdx.x * 256 + threadIdx.x;   // 65536 threads
    g_cnt[t] = 0;
    if (t < DB) g_base[t] = 0;
    if (t < DD * DD) {
        int k = t & 127;
        int n = t >> 7;
        float v = W[n * DD + k];
        __nv_bfloat16 hi = __float2bfloat16_rn(v);
        __nv_bfloat16 lo = __float2bfloat16_rn(v - __bfloat162float(hi));
        g_Whi[k * DD + n] = hi;
        g_Wlo[k * DD + n] = lo;
    }
    if (t == 0) {
        // int64 values < 8192 -> all odd 32-bit words zero (little-endian)
        int ok = 1;
        for (int i = 0; i < 64; i++)
            if (eiw[2 * i + 1] != 0u) { ok = 0; break; }
        g_is64 = ok;
    }
}

__device__ __forceinline__ int load_idx(const void* ei, size_t p) {
    return g_is64 ? (int)((const long long*)ei)[p] : ((const int*)ei)[p];
}

// ---------------------------------------------------------------------------
// histogram of dst degrees
// ---------------------------------------------------------------------------
__global__ void hist_kernel(const void* __restrict__ ei) {
    int t = blockIdx.x * 256 + threadIdx.x;    // [0, DB*DE)
    int b = t >> 17;
    int e = t & (DE - 1);
    int dst = load_idx(ei, ((size_t)b * 2 + 1) * DE + e);
    if ((unsigned)dst < DN) atomicAdd(&g_cnt[b * DN + dst], 1);
}

// ---------------------------------------------------------------------------
// region allocation: warp-scan + one atomicAdd per warp per batch cursor.
// ---------------------------------------------------------------------------
__global__ void alloc_kernel() {
    int node = blockIdx.x * 256 + threadIdx.x;   // [0, 65536)
    int lane = threadIdx.x & 31;
    int b = node >> 13;
    int cnt = g_cnt[node];
    int incl = cnt;
#pragma unroll
    for (int o = 1; o < 32; o <<= 1) {
        int n = __shfl_up_sync(0xFFFFFFFFu, incl, o);
        if (lane >= o) incl += n;
    }
    int total = __shfl_sync(0xFFFFFFFFu, incl, 31);
    int base = 0;
    if (lane == 31) base = atomicAdd(&g_base[b], total);
    base = __shfl_sync(0xFFFFFFFFu, base, 31);
    int off = base + incl - cnt;
    g_off[node] = off;
    g_cur[node] = off;
}

// ---------------------------------------------------------------------------
// Tensor-core GEMM (mma.sync, bf16 3-term split) FUSED with edge scatter.
// Blocks [0,512): one 128-row GEMM tile, 512 threads, 16 warps.
//   Warp tile = 16 rows x 64 cols (8 m-groups x 2 n-halves, 4 warps/SMSP).
//   Per kt: load ALL B frags first, then 3 passes of 8 INDEPENDENT MMAs
//   (hi*hi, lo*hi, hi*lo) -> accumulator RAW chains broken by 8-MMA gaps.
// Blocks [512,768): scatter src ids into dst-sorted order (backfills SMs).
// ---------------------------------------------------------------------------
__device__ __forceinline__ void ldsm_x4(unsigned* r, unsigned addr) {
    asm volatile("ldmatrix.sync.aligned.m8n8.x4.shared.b16 {%0,%1,%2,%3}, [%4];"
                 : "=r"(r[0]), "=r"(r[1]), "=r"(r[2]), "=r"(r[3]) : "r"(addr));
}
__device__ __forceinline__ void ldsm_x4_t(unsigned* r, unsigned addr) {
    asm volatile("ldmatrix.sync.aligned.m8n8.x4.trans.shared.b16 {%0,%1,%2,%3}, [%4];"
                 : "=r"(r[0]), "=r"(r[1]), "=r"(r[2]), "=r"(r[3]) : "r"(addr));
}
__device__ __forceinline__ void mma_bf16(float* c, const unsigned* a,
                                         unsigned b0, unsigned b1) {
    asm("mma.sync.aligned.m16n8k16.row.col.f32.bf16.bf16.f32 "
        "{%0,%1,%2,%3}, {%4,%5,%6,%7}, {%8,%9}, {%0,%1,%2,%3};"
        : "+f"(c[0]), "+f"(c[1]), "+f"(c[2]), "+f"(c[3])
        : "r"(a[0]), "r"(a[1]), "r"(a[2]), "r"(a[3]), "r"(b0), "r"(b1));
}

__device__ __forceinline__ void split8(float4 f0, float4 f1, uint4& hi, uint4& lo) {
    float f[8] = {f0.x, f0.y, f0.z, f0.w, f1.x, f1.y, f1.z, f1.w};
    unsigned h[4], l[4];
#pragma unroll
    for (int i = 0; i < 4; i++) {
        __nv_bfloat162 hh = __floats2bfloat162_rn(f[2 * i], f[2 * i + 1]);
        float r0 = f[2 * i]     - __bfloat162float(hh.x);
        float r1 = f[2 * i + 1] - __bfloat162float(hh.y);
        __nv_bfloat162 ll = __floats2bfloat162_rn(r0, r1);
        h[i] = *(unsigned*)&hh;
        l[i] = *(unsigned*)&ll;
    }
    hi = make_uint4(h[0], h[1], h[2], h[3]);
    lo = make_uint4(l[0], l[1], l[2], l[3]);
}

__global__ void __launch_bounds__(512)
gemm_scatter_kernel(const float* __restrict__ x, const float* __restrict__ bias,
                    const void* __restrict__ ei) {
    // ---- scatter blocks -------------------------------------------------
    if (blockIdx.x >= 512) {
        int tbase = (blockIdx.x - 512) * 512 + threadIdx.x;   // [0, 131072)
#pragma unroll
        for (int i = 0; i < 8; i++) {
            int t = tbase + i * 131072;                       // [0, DB*DE)
            int b = t >> 17;
            int e = t & (DE - 1);
            int src = load_idx(ei, (size_t)b * 2 * DE + e);
            int dst = load_idx(ei, ((size_t)b * 2 + 1) * DE + e);
            if ((unsigned)src >= DN || (unsigned)dst >= DN) continue;
            int pos = atomicAdd(&g_cur[b * DN + dst], 1);
            g_srt[(size_t)b * DE + pos] = src;
        }
        return;
    }

    // ---- GEMM blocks ----------------------------------------------------
    extern __shared__ char smc[];
    __nv_bfloat16* sWhi = (__nv_bfloat16*)smc;              // [128][128] swz (+32768B lo)
    __nv_bfloat16* sXhi = (__nv_bfloat16*)(smc + 65536);    // [128][128] swz (+32768B lo)

    int tid = threadIdx.x;
    int row0 = blockIdx.x * 128;

    // copy pre-split W planes (bf16, k-major), 16B chunks with swizzle
    for (int c = tid; c < 2048; c += 512) {
        int row = c >> 4, j = c & 15;
        int off = row * DD + ((j ^ (row & 7)) << 3);
        *(uint4*)(sWhi + off)                  = *(const uint4*)(g_Whi + row * DD + j * 8);
        *(uint4*)((char*)(sWhi + off) + 32768) = *(const uint4*)(g_Wlo + row * DD + j * 8);
    }
    // load + split X (128 rows)
    for (int c = tid; c < 2048; c += 512) {
        int row = c >> 4, j = c & 15;
        const float4* p = (const float4*)(x + (size_t)(row0 + row) * DD + j * 8);
        uint4 hi, lo;
        split8(p[0], p[1], hi, lo);
        int off = row * DD + ((j ^ (row & 7)) << 3);
        *(uint4*)(sXhi + off)                  = hi;
        *(uint4*)((char*)(sXhi + off) + 32768) = lo;
    }
    __syncthreads();

    int warp = tid >> 5, lane = tid & 31;
    int m0 = (warp >> 1) * 16;        // 0..112
    int nh = warp & 1;                // n-half: cols nh*64 .. nh*64+63
    int l15 = lane & 15, lh = lane >> 4;

    int arow = m0 + l15;
    unsigned xbhi = (unsigned)__cvta_generic_to_shared(sXhi) + arow * 256;
    unsigned xsw = (unsigned)(arow & 7);
    unsigned wb = (unsigned)__cvta_generic_to_shared(sWhi);

    float acc[8][4];
#pragma unroll
    for (int t = 0; t < 8; t++)
#pragma unroll
        for (int i = 0; i < 4; i++) acc[t][i] = 0.f;

#pragma unroll
    for (int kt = 0; kt < 8; kt++) {
        // load A fragments (hi+lo)
        unsigned ahi[4], alo[4];
        unsigned achunk = (((unsigned)(2 * kt + lh)) ^ xsw) << 4;
        ldsm_x4(ahi, xbhi + achunk);
        ldsm_x4(alo, xbhi + achunk + 32768u);
        // load ALL B fragments for this warp's n-range first
        int brow = kt * 16 + l15;
        unsigned bb = wb + brow * 256;
        unsigned bsw = (unsigned)(brow & 7);
        unsigned bhi[4][4], blo[4][4];
#pragma unroll
        for (int t2 = 0; t2 < 4; t2++) {
            unsigned bchunk = (((unsigned)(nh * 8 + 2 * t2 + lh)) ^ bsw) << 4;
            ldsm_x4_t(bhi[t2], bb + bchunk);
            ldsm_x4_t(blo[t2], bb + bchunk + 32768u);
        }
        // pass 1: hi*hi — 8 independent MMAs
#pragma unroll
        for (int t2 = 0; t2 < 4; t2++) {
            mma_bf16(acc[2 * t2],     ahi, bhi[t2][0], bhi[t2][1]);
            mma_bf16(acc[2 * t2 + 1], ahi, bhi[t2][2], bhi[t2][3]);
        }
        // pass 2: lo*hi — 8 independent MMAs (8-MMA gap from pass 1)
#pragma unroll
        for (int t2 = 0; t2 < 4; t2++) {
            mma_bf16(acc[2 * t2],     alo, bhi[t2][0], bhi[t2][1]);
            mma_bf16(acc[2 * t2 + 1], alo, bhi[t2][2], bhi[t2][3]);
        }
        // pass 3: hi*lo
#pragma unroll
        for (int t2 = 0; t2 < 4; t2++) {
            mma_bf16(acc[2 * t2],     ahi, blo[t2][0], blo[t2][1]);
            mma_bf16(acc[2 * t2 + 1], ahi, blo[t2][2], blo[t2][3]);
        }
    }

    // epilogue: C frag lane mapping: rows g, g+8; cols nh*64 + 8t + 2q (+1)
    int g = lane >> 2;
    int q = lane & 3;
    size_t r0g = (size_t)(row0 + m0 + g) * DD;
    float*  h0  = g_h  + r0g;
    float*  h1  = h0 + 8 * DD;
    __half* hh0 = g_hh + r0g;
    __half* hh1 = hh0 + 8 * DD;
#pragma unroll
    for (int t = 0; t < 8; t++) {
        int n = nh * 64 + 8 * t + 2 * q;
        float2 bv = *(const float2*)(bias + n);
        float2 v0 = make_float2(acc[t][0] + bv.x, acc[t][1] + bv.y);
        float2 v1 = make_float2(acc[t][2] + bv.x, acc[t][3] + bv.y);
        *(float2*)(h0 + n) = v0;
        *(float2*)(h1 + n) = v1;
        *(__half2*)(hh0 + n) = __floats2half2_rn(v0.x, v0.y);
        *(__half2*)(hh1 + n) = __floats2half2_rn(v1.x, v1.y);
    }
}

// ---------------------------------------------------------------------------
// Fused: CSR gather of incident src rows (fp16), + fp32 h, LN, ReLU, mask.
// One warp per node; 8 rows in flight per iteration for L2-latency hiding.
// ---------------------------------------------------------------------------
__global__ void agg_ln_kernel(const float* __restrict__ mask,
                              const float* __restrict__ gamma,
                              const float* __restrict__ beta,
                              float* __restrict__ out) {
    int w = (blockIdx.x * 256 + threadIdx.x) >> 5;   // node id [0, 65536)
    int lane = threadIdx.x & 31;
    int b = w >> 13;

    int start = g_off[w];
    int cnt = g_cnt[w];
    int end = start + cnt;
    const int* srt = g_srt + (size_t)b * DE;
    const __half* hb = g_hh + (size_t)b * DN * DD;

    float4 acc = make_float4(0.f, 0.f, 0.f, 0.f);
    int j = start;
    for (; j + 8 <= end; j += 8) {
        int s[8];
#pragma unroll
        for (int i = 0; i < 8; i++) s[i] = srt[j + i];
        uint2 r[8];
#pragma unroll
        for (int i = 0; i < 8; i++)
            r[i] = ((const uint2*)(hb + (size_t)s[i] * DD))[lane];
#pragma unroll
        for (int i = 0; i < 8; i++) {
            float2 a = __half22float2(*(__half2*)&r[i].x);
            float2 c = __half22float2(*(__half2*)&r[i].y);
            acc.x += a.x; acc.y += a.y; acc.z += c.x; acc.w += c.y;
        }
    }
    for (; j + 4 <= end; j += 4) {
        int s[4];
#pragma unroll
        for (int i = 0; i < 4; i++) s[i] = srt[j + i];
        uint2 r[4];
#pragma unroll
        for (int i = 0; i < 4; i++)
            r[i] = ((const uint2*)(hb + (size_t)s[i] * DD))[lane];
#pragma unroll
        for (int i = 0; i < 4; i++) {
            float2 a = __half22float2(*(__half2*)&r[i].x);
            float2 c = __half22float2(*(__half2*)&r[i].y);
            acc.x += a.x; acc.y += a.y; acc.z += c.x; acc.w += c.y;
        }
    }
    for (; j < end; j++) {
        int s0 = srt[j];
        uint2 r0 = ((const uint2*)(hb + (size_t)s0 * DD))[lane];
        float2 a0 = __half22float2(*(__half2*)&r0.x), b0 = __half22float2(*(__half2*)&r0.y);
        acc.x += a0.x; acc.y += a0.y; acc.z += b0.x; acc.w += b0.y;
    }

    float4 h = ((const float4*)(g_h + (size_t)w * DD))[lane];
    const float s = 0.011048543456039806f;  // 1/sqrt(8192)
    float4 v;
    v.x = h.x + acc.x * s;
    v.y = h.y + acc.y * s;
    v.z = h.z + acc.z * s;
    v.w = h.w + acc.w * s;

    float sum = v.x + v.y + v.z + v.w;
    float ssq = v.x * v.x + v.y * v.y + v.z * v.z + v.w * v.w;
#pragma unroll
    for (int o = 16; o > 0; o >>= 1) {
        sum += __shfl_xor_sync(0xFFFFFFFFu, sum, o);
        ssq += __shfl_xor_sync(0xFFFFFFFFu, ssq, o);
    }
    float mu = sum * (1.0f / 128.0f);
    float var = ssq * (1.0f / 128.0f) - mu * mu;
    float rstd = rsqrtf(var + 1e-5f);
    float m = mask[w];

    float4 gg = ((const float4*)gamma)[lane];
    float4 be = ((const float4*)beta)[lane];
    float4 o4;
    o4.x = fmaxf((v.x - mu) * rstd * gg.x + be.x, 0.f) * m;
    o4.y = fmaxf((v.y - mu) * rstd * gg.y + be.y, 0.f) * m;
    o4.z = fmaxf((v.z - mu) * rstd * gg.z + be.z, 0.f) * m;
    o4.w = fmaxf((v.w - mu) * rstd * gg.w + be.w, 0.f) * m;

    ((float4*)out)[(size_t)w * 32 + lane] = o4;
}

// ---------------------------------------------------------------------------
extern "C" void kernel_launch(void* const* d_in, const int* in_sizes, int n_in,
                              void* d_out, int out_size) {
    const float* xf     = (const float*)d_in[0];   // node_features [8,8192,128]
    const void*  ei     = d_in[1];                 // edge_index [8,2,131072]
    const float* mask   = (const float*)d_in[2];   // node_mask [8,8192]
    const float* W      = (const float*)d_in[3];   // W [128,128]
    const float* bias   = (const float*)d_in[4];   // b [128]
    const float* gamma  = (const float*)d_in[5];   // gamma [128]
    const float* beta   = (const float*)d_in[6];   // beta [128]
    float* out          = (float*)d_out;

    const int smem_bytes = 131072;  // 4 x 32 KB bf16 planes
    cudaFuncSetAttribute(gemm_scatter_kernel,
                         cudaFuncAttributeMaxDynamicSharedMemorySize, smem_bytes);

    setup_kernel<<<(DB * DN) / 256, 256>>>((const unsigned*)ei, W);
    hist_kernel<<<(DB * DE) / 256, 256>>>(ei);
    alloc_kernel<<<(DB * DN) / 256, 256>>>();
    gemm_scatter_kernel<<<768, 512, smem_bytes>>>(xf, bias, ei);   // 512 gemm + 256 scatter
    agg_ln_kernel<<<(DB * DN) / 8, 256>>>(mask, gamma, beta, out); // 8192 blocks
}

// round 17
// speedup vs baseline: 1.5524x; 1.0858x over previous
#include <cuda_runtime.h>
#include <cuda_fp16.h>
#include <cuda_bf16.h>

#define DB 8
#define DN 8192
#define DE 131072
#define DD 128
// 65536 rows total; gemm: 512 blocks x 2 tiles x 64 rows

__device__ float         g_h[DB * DN * DD];    // 32 MB: linear output (fp32)
__device__ __half        g_hh[DB * DN * DD];   // 16 MB: fp16 copy for gathers
__device__ __nv_bfloat16 g_Whi[DD * DD];       // W split hi, native [n][k]
__device__ __nv_bfloat16 g_Wlo[DD * DD];       // W split lo, native [n][k]
__device__ int           g_cnt[DB * DN];       // per-dst edge counts
__device__ int           g_off[DB * DN];       // CSR start offsets
__device__ int           g_cur[DB * DN];       // scatter cursors
__device__ int           g_srt[DB * DE];       // src indices sorted by dst
__device__ int           g_base[DB];           // per-batch region allocator
__device__ int           g_is64;               // edge_index dtype flag

// ---------------------------------------------------------------------------
// setup: detect idx dtype + zero counters + split W (native [n][k], no transpose)
// ---------------------------------------------------------------------------
__global__ void setup_kernel(const unsigned* __restrict__ eiw,
                             const float* __restrict__ W) {
    int t = blockIdx.x * 256 + threadIdx.x;   // 65536 threads
    g_cnt[t] = 0;
    if (t < DB) g_base[t] = 0;
    if (t < DD * DD) {
        float v = W[t];
        __nv_bfloat16 hi = __float2bfloat16_rn(v);
        __nv_bfloat16 lo = __float2bfloat16_rn(v - __bfloat162float(hi));
        g_Whi[t] = hi;
        g_Wlo[t] = lo;
    }
    if (t == 0) {
        // int64 values < 8192 -> all odd 32-bit words zero (little-endian)
        int ok = 1;
        for (int i = 0; i < 64; i++)
            if (eiw[2 * i + 1] != 0u) { ok = 0; break; }
        g_is64 = ok;
    }
}

__device__ __forceinline__ int load_idx(const void* ei, size_t p) {
    return g_is64 ? (int)((const long long*)ei)[p] : ((const int*)ei)[p];
}

// ---------------------------------------------------------------------------
// histogram of dst degrees
// ---------------------------------------------------------------------------
__global__ void hist_kernel(const void* __restrict__ ei) {
    int t = blockIdx.x * 256 + threadIdx.x;    // [0, DB*DE)
    int b = t >> 17;
    int e = t & (DE - 1);
    int dst = load_idx(ei, ((size_t)b * 2 + 1) * DE + e);
    if ((unsigned)dst < DN) atomicAdd(&g_cnt[b * DN + dst], 1);
}

// ---------------------------------------------------------------------------
// region allocation: warp-scan + one atomicAdd per warp per batch cursor.
// ---------------------------------------------------------------------------
__global__ void alloc_kernel() {
    int node = blockIdx.x * 256 + threadIdx.x;   // [0, 65536)
    int lane = threadIdx.x & 31;
    int b = node >> 13;
    int cnt = g_cnt[node];
    int incl = cnt;
#pragma unroll
    for (int o = 1; o < 32; o <<= 1) {
        int n = __shfl_up_sync(0xFFFFFFFFu, incl, o);
        if (lane >= o) incl += n;
    }
    int total = __shfl_sync(0xFFFFFFFFu, incl, 31);
    int base = 0;
    if (lane == 31) base = atomicAdd(&g_base[b], total);
    base = __shfl_sync(0xFFFFFFFFu, base, 31);
    int off = base + incl - cnt;
    g_off[node] = off;
    g_cur[node] = off;
}

// ---------------------------------------------------------------------------
// ldmatrix / mma helpers
// ---------------------------------------------------------------------------
__device__ __forceinline__ void ldsm_x4(unsigned* r, unsigned addr) {
    asm volatile("ldmatrix.sync.aligned.m8n8.x4.shared.b16 {%0,%1,%2,%3}, [%4];"
                 : "=r"(r[0]), "=r"(r[1]), "=r"(r[2]), "=r"(r[3]) : "r"(addr));
}
__device__ __forceinline__ void mma_bf16(float* c, const unsigned* a,
                                         unsigned b0, unsigned b1) {
    asm("mma.sync.aligned.m16n8k16.row.col.f32.bf16.bf16.f32 "
        "{%0,%1,%2,%3}, {%4,%5,%6,%7}, {%8,%9}, {%0,%1,%2,%3};"
        : "+f"(c[0]), "+f"(c[1]), "+f"(c[2]), "+f"(c[3])
        : "r"(a[0]), "r"(a[1]), "r"(a[2]), "r"(a[3]), "r"(b0), "r"(b1));
}

__device__ __forceinline__ void split8(float4 f0, float4 f1, uint4& hi, uint4& lo) {
    float f[8] = {f0.x, f0.y, f0.z, f0.w, f1.x, f1.y, f1.z, f1.w};
    unsigned h[4], l[4];
#pragma unroll
    for (int i = 0; i < 4; i++) {
        __nv_bfloat162 hh = __floats2bfloat162_rn(f[2 * i], f[2 * i + 1]);
        float r0 = f[2 * i]     - __bfloat162float(hh.x);
        float r1 = f[2 * i + 1] - __bfloat162float(hh.y);
        __nv_bfloat162 ll = __floats2bfloat162_rn(r0, r1);
        h[i] = *(unsigned*)&hh;
        l[i] = *(unsigned*)&ll;
    }
    hi = make_uint4(h[0], h[1], h[2], h[3]);
    lo = make_uint4(l[0], l[1], l[2], l[3]);
}

// ---------------------------------------------------------------------------
// Tensor-core GEMM (mma.sync, bf16 3-term split) FUSED with edge scatter.
// Blocks [0,512): 2 sequential 64-row tiles each. 512 thr; warp tile 16x32
//   (4 m-groups x 4 n-groups). smem = W hi/lo 64K + X hi/lo 32K = 96 KB
//   -> 2 blocks/SM (8 warps/SMSP). W native [n][k], B via NON-trans ldmatrix.
// Blocks [512,768): scatter src ids into dst-sorted order (backfills SMs).
// ---------------------------------------------------------------------------
__global__ void __launch_bounds__(512, 2)
gemm_scatter_kernel(const float* __restrict__ x, const float* __restrict__ bias,
                    const void* __restrict__ ei) {
    // ---- scatter blocks -------------------------------------------------
    if (blockIdx.x >= 512) {
        int tbase = (blockIdx.x - 512) * 512 + threadIdx.x;   // [0, 131072)
#pragma unroll
        for (int i = 0; i < 8; i++) {
            int t = tbase + i * 131072;                       // [0, DB*DE)
            int b = t >> 17;
            int e = t & (DE - 1);
            int src = load_idx(ei, (size_t)b * 2 * DE + e);
            int dst = load_idx(ei, ((size_t)b * 2 + 1) * DE + e);
            if ((unsigned)src >= DN || (unsigned)dst >= DN) continue;
            int pos = atomicAdd(&g_cur[b * DN + dst], 1);
            g_srt[(size_t)b * DE + pos] = src;
        }
        return;
    }

    // ---- GEMM blocks ----------------------------------------------------
    extern __shared__ char smc[];
    __nv_bfloat16* sWhi = (__nv_bfloat16*)smc;              // [128 n][128 k] swz (+32768B lo)
    __nv_bfloat16* sXhi = (__nv_bfloat16*)(smc + 65536);    // [64 m][128 k]  swz (+16384B lo)

    int tid = threadIdx.x;

    // W planes (pre-split bf16, native n-major), 16B chunks with swizzle
    for (int c = tid; c < 2048; c += 512) {
        int row = c >> 4, j = c & 15;
        int off = row * DD + ((j ^ (row & 7)) << 3);
        *(uint4*)(sWhi + off)                  = *(const uint4*)(g_Whi + row * DD + j * 8);
        *(uint4*)((char*)(sWhi + off) + 32768) = *(const uint4*)(g_Wlo + row * DD + j * 8);
    }

    int warp = tid >> 5, lane = tid & 31;
    int m0 = (warp >> 2) * 16;        // 0,16,32,48
    int n0 = (warp & 3) * 32;         // 0,32,64,96
    int l15 = lane & 15, lh = lane >> 4;

    unsigned wb  = (unsigned)__cvta_generic_to_shared(sWhi);
    unsigned xb  = (unsigned)__cvta_generic_to_shared(sXhi);
    // B addresses: row = n0 + nt*16 + l15, chunk = (2kt+lh) ^ (row&7)
    int brow0 = n0 + l15;
    int brow1 = n0 + 16 + l15;
    unsigned bb0 = wb + brow0 * 256, bsw0 = (unsigned)(brow0 & 7);
    unsigned bb1 = wb + brow1 * 256, bsw1 = (unsigned)(brow1 & 7);
    int arow = m0 + l15;
    unsigned ab = xb + arow * 256, asw = (unsigned)(arow & 7);

#pragma unroll 1
    for (int tile = 0; tile < 2; tile++) {
        int row0 = blockIdx.x * 128 + tile * 64;

        // load + split X (64 rows): 1024 chunks / 512 thr = 2 iters
        __syncthreads();
        for (int c = tid; c < 1024; c += 512) {
            int row = c >> 4, j = c & 15;
            const float4* p = (const float4*)(x + (size_t)(row0 + row) * DD + j * 8);
            uint4 hi, lo;
            split8(p[0], p[1], hi, lo);
            int off = row * DD + ((j ^ (row & 7)) << 3);
            *(uint4*)(sXhi + off)                  = hi;
            *(uint4*)((char*)(sXhi + off) + 16384) = lo;
        }
        __syncthreads();

        float acc[4][4];
#pragma unroll
        for (int t = 0; t < 4; t++)
#pragma unroll
            for (int i = 0; i < 4; i++) acc[t][i] = 0.f;

#pragma unroll
        for (int kt = 0; kt < 8; kt++) {
            unsigned kch = (unsigned)(2 * kt + lh);
            // A frags (hi+lo): r = [{m0,k0},{m8,k0},{m0,k1},{m8,k1}] = a0..a3
            unsigned ahi[4], alo[4];
            unsigned ac = (kch ^ asw) << 4;
            ldsm_x4(ahi, ab + ac);
            ldsm_x4(alo, ab + ac + 16384u);
            // B frags, non-trans: r = [{n0-7,k0},{n8-15,k0},{n0-7,k1},{n8-15,k1}]
            // -> n-tile j frag = {r[j], r[j+2]}
            unsigned bh0[4], bh1[4], bl0[4], bl1[4];
            unsigned bc0 = (kch ^ bsw0) << 4;
            unsigned bc1 = (kch ^ bsw1) << 4;
            ldsm_x4(bh0, bb0 + bc0);
            ldsm_x4(bh1, bb1 + bc1);
            ldsm_x4(bl0, bb0 + bc0 + 32768u);
            ldsm_x4(bl1, bb1 + bc1 + 32768u);
            // pass 1: hi*hi — 4 independent MMAs
            mma_bf16(acc[0], ahi, bh0[0], bh0[2]);
            mma_bf16(acc[1], ahi, bh0[1], bh0[3]);
            mma_bf16(acc[2], ahi, bh1[0], bh1[2]);
            mma_bf16(acc[3], ahi, bh1[1], bh1[3]);
            // pass 2: lo*hi
            mma_bf16(acc[0], alo, bh0[0], bh0[2]);
            mma_bf16(acc[1], alo, bh0[1], bh0[3]);
            mma_bf16(acc[2], alo, bh1[0], bh1[2]);
            mma_bf16(acc[3], alo, bh1[1], bh1[3]);
            // pass 3: hi*lo
            mma_bf16(acc[0], ahi, bl0[0], bl0[2]);
            mma_bf16(acc[1], ahi, bl0[1], bl0[3]);
            mma_bf16(acc[2], ahi, bl1[0], bl1[2]);
            mma_bf16(acc[3], ahi, bl1[1], bl1[3]);
        }

        // epilogue: rows g, g+8; cols n0 + 8t + 2q (+1)
        int g = lane >> 2;
        int q = lane & 3;
        size_t r0g = (size_t)(row0 + m0 + g) * DD;
        float*  h0  = g_h  + r0g;
        float*  h1  = h0 + 8 * DD;
        __half* hh0 = g_hh + r0g;
        __half* hh1 = hh0 + 8 * DD;
#pragma unroll
        for (int t = 0; t < 4; t++) {
            int n = n0 + 8 * t + 2 * q;
            float2 bv = *(const float2*)(bias + n);
            float2 v0 = make_float2(acc[t][0] + bv.x, acc[t][1] + bv.y);
            float2 v1 = make_float2(acc[t][2] + bv.x, acc[t][3] + bv.y);
            *(float2*)(h0 + n) = v0;
            *(float2*)(h1 + n) = v1;
            *(__half2*)(hh0 + n) = __floats2half2_rn(v0.x, v0.y);
            *(__half2*)(hh1 + n) = __floats2half2_rn(v1.x, v1.y);
        }
    }
}

// ---------------------------------------------------------------------------
// Fused: CSR gather of incident src rows (fp16), + fp32 h, LN, ReLU, mask.
// One warp per node; 8 rows in flight per iteration for L2-latency hiding.
// ---------------------------------------------------------------------------
__global__ void agg_ln_kernel(const float* __restrict__ mask,
                              const float* __restrict__ gamma,
                              const float* __restrict__ beta,
                              float* __restrict__ out) {
    int w = (blockIdx.x * 256 + threadIdx.x) >> 5;   // node id [0, 65536)
    int lane = threadIdx.x & 31;
    int b = w >> 13;

    int start = g_off[w];
    int cnt = g_cnt[w];
    int end = start + cnt;
    const int* srt = g_srt + (size_t)b * DE;
    const __half* hb = g_hh + (size_t)b * DN * DD;

    float4 acc = make_float4(0.f, 0.f, 0.f, 0.f);
    int j = start;
    for (; j + 8 <= end; j += 8) {
        int s[8];
#pragma unroll
        for (int i = 0; i < 8; i++) s[i] = srt[j + i];
        uint2 r[8];
#pragma unroll
        for (int i = 0; i < 8; i++)
            r[i] = ((const uint2*)(hb + (size_t)s[i] * DD))[lane];
#pragma unroll
        for (int i = 0; i < 8; i++) {
            float2 a = __half22float2(*(__half2*)&r[i].x);
            float2 c = __half22float2(*(__half2*)&r[i].y);
            acc.x += a.x; acc.y += a.y; acc.z += c.x; acc.w += c.y;
        }
    }
    for (; j + 4 <= end; j += 4) {
        int s[4];
#pragma unroll
        for (int i = 0; i < 4; i++) s[i] = srt[j + i];
        uint2 r[4];
#pragma unroll
        for (int i = 0; i < 4; i++)
            r[i] = ((const uint2*)(hb + (size_t)s[i] * DD))[lane];
#pragma unroll
        for (int i = 0; i < 4; i++) {
            float2 a = __half22float2(*(__half2*)&r[i].x);
            float2 c = __half22float2(*(__half2*)&r[i].y);
            acc.x += a.x; acc.y += a.y; acc.z += c.x; acc.w += c.y;
        }
    }
    for (; j < end; j++) {
        int s0 = srt[j];
        uint2 r0 = ((const uint2*)(hb + (size_t)s0 * DD))[lane];
        float2 a0 = __half22float2(*(__half2*)&r0.x), b0 = __half22float2(*(__half2*)&r0.y);
        acc.x += a0.x; acc.y += a0.y; acc.z += b0.x; acc.w += b0.y;
    }

    float4 h = ((const float4*)(g_h + (size_t)w * DD))[lane];
    const float s = 0.011048543456039806f;  // 1/sqrt(8192)
    float4 v;
    v.x = h.x + acc.x * s;
    v.y = h.y + acc.y * s;
    v.z = h.z + acc.z * s;
    v.w = h.w + acc.w * s;

    float sum = v.x + v.y + v.z + v.w;
    float ssq = v.x * v.x + v.y * v.y + v.z * v.z + v.w * v.w;
#pragma unroll
    for (int o = 16; o > 0; o >>= 1) {
        sum += __shfl_xor_sync(0xFFFFFFFFu, sum, o);
        ssq += __shfl_xor_sync(0xFFFFFFFFu, ssq, o);
    }
    float mu = sum * (1.0f / 128.0f);
    float var = ssq * (1.0f / 128.0f) - mu * mu;
    float rstd = rsqrtf(var + 1e-5f);
    float m = mask[w];

    float4 gg = ((const float4*)gamma)[lane];
    float4 be = ((const float4*)beta)[lane];
    float4 o4;
    o4.x = fmaxf((v.x - mu) * rstd * gg.x + be.x, 0.f) * m;
    o4.y = fmaxf((v.y - mu) * rstd * gg.y + be.y, 0.f) * m;
    o4.z = fmaxf((v.z - mu) * rstd * gg.z + be.z, 0.f) * m;
    o4.w = fmaxf((v.w - mu) * rstd * gg.w + be.w, 0.f) * m;

    ((float4*)out)[(size_t)w * 32 + lane] = o4;
}

// ---------------------------------------------------------------------------
extern "C" void kernel_launch(void* const* d_in, const int* in_sizes, int n_in,
                              void* d_out, int out_size) {
    const float* xf     = (const float*)d_in[0];   // node_features [8,8192,128]
    const void*  ei     = d_in[1];                 // edge_index [8,2,131072]
    const float* mask   = (const float*)d_in[2];   // node_mask [8,8192]
    const float* W      = (const float*)d_in[3];   // W [128,128]
    const float* bias   = (const float*)d_in[4];   // b [128]
    const float* gamma  = (const float*)d_in[5];   // gamma [128]
    const float* beta   = (const float*)d_in[6];   // beta [128]
    float* out          = (float*)d_out;

    const int smem_bytes = 98304;  // W hi/lo 64 KB + X hi/lo 32 KB
    cudaFuncSetAttribute(gemm_scatter_kernel,
                         cudaFuncAttributeMaxDynamicSharedMemorySize, smem_bytes);

    setup_kernel<<<(DB * DN) / 256, 256>>>((const unsigned*)ei, W);
    hist_kernel<<<(DB * DE) / 256, 256>>>(ei);
    alloc_kernel<<<(DB * DN) / 256, 256>>>();
    gemm_scatter_kernel<<<768, 512, smem_bytes>>>(xf, bias, ei);   // 512 gemm + 256 scatter
    agg_ln_kernel<<<(DB * DN) / 8, 256>>>(mask, gamma, beta, out); // 8192 blocks
}